// round 4
// baseline (speedup 1.0000x reference)
#include <cuda_runtime.h>
#include <math.h>

#define NQ   6
#define DIM  64
#define TS   64
#define PADB 68    // b-operand arrays (float4 GEMM access)
#define PADD 132   // duplicated a-operand arrays ({v,v} pairs)
#define PADH 66    // H / probs row arrays (even pitch, paired stores)
#define PADM 65    // MzT rows

typedef unsigned long long ull;

__device__ float g_CRT[DIM * DIM];
__device__ float g_CIT[DIM * DIM];
__device__ float g_MzT[5 * PADM];

__device__ __forceinline__ void ffma2(ull &d, ull a, ull b) {
    asm("fma.rn.f32x2 %0, %1, %2, %0;" : "+l"(d) : "l"(a), "l"(b));
}

__device__ __forceinline__ int ring_map(int r, int i) {
    int v = i;
    for (int w = NQ - 1; w >= 0; --w) {
        int t = (w + r) % NQ;
        v ^= ((v >> (NQ - 1 - w)) & 1) << (NQ - 1 - t);
    }
    return v;
}

// One block, 64 threads. Thread j owns column j of C.
__global__ void setup_kernel(const float* __restrict__ th_sh,
                             const float* __restrict__ th_tk,
                             const float* __restrict__ Wc) {
    __shared__ float2 C[DIM][DIM];
    int j = threadIdx.x;
    if (j >= DIM) return;
    for (int i = 0; i < DIM; i++) C[i][j] = make_float2(i == j ? 1.f : 0.f, 0.f);

    const float* TH[3] = { th_sh, th_sh + NQ * 3, th_tk };
    const int    RS[3] = { 1, 2, 1 };

    for (int l = 0; l < 3; l++) {
        const float* th = TH[l];
        for (int w = 0; w < NQ; w++) {
            float phi = th[w * 3 + 0], te = th[w * 3 + 1], om = th[w * 3 + 2];
            float sth, cth; sincosf(0.5f * te, &sth, &cth);
            float a = 0.5f * (phi + om), b = 0.5f * (phi - om);
            float sa, ca, sb, cb;
            sincosf(a, &sa, &ca);
            sincosf(b, &sb, &cb);
            float2 R00 = make_float2( ca * cth, -sa * cth);
            float2 R01 = make_float2(-cb * sth, -sb * sth);
            float2 R10 = make_float2( cb * sth, -sb * sth);
            float2 R11 = make_float2( ca * cth,  sa * cth);
            int bit = 1 << (NQ - 1 - w);
            for (int i0 = 0; i0 < DIM; i0++) {
                if (i0 & bit) continue;
                int i1 = i0 | bit;
                float2 v0 = C[i0][j], v1 = C[i1][j];
                C[i0][j] = make_float2(
                    R00.x * v0.x - R00.y * v0.y + R01.x * v1.x - R01.y * v1.y,
                    R00.x * v0.y + R00.y * v0.x + R01.x * v1.y + R01.y * v1.x);
                C[i1][j] = make_float2(
                    R10.x * v0.x - R10.y * v0.y + R11.x * v1.x - R11.y * v1.y,
                    R10.x * v0.y + R10.y * v0.x + R11.x * v1.y + R11.y * v1.x);
            }
        }
        float2 tmp[DIM];
        for (int i = 0; i < DIM; i++) tmp[i] = C[ring_map(RS[l], i)][j];
        for (int i = 0; i < DIM; i++) C[i][j] = tmp[i];
    }
    for (int i = 0; i < DIM; i++) {
        g_CRT[j * DIM + i] = C[i][j].x;
        g_CIT[j * DIM + i] = C[i][j].y;
    }
    for (int o = 0; o < 5; o++) {
        float s = 0.f;
        for (int q = 0; q < NQ; q++) {
            float zs = ((j >> (NQ - 1 - q)) & 1) ? -1.f : 1.f;
            s += zs * Wc[o * NQ + q];
        }
        g_MzT[o * PADM + j] = s;
    }
}

// smem layout (floats)
#define OFF_W1T  0
#define OFF_CRT  (OFF_W1T + DIM * PADB)          // 4352
#define OFF_CIT  (OFF_CRT + DIM * PADB)          // 8704
#define OFF_ADUP (OFF_CIT + DIM * PADB)          // 13056
#define OFF_H    (OFF_ADUP + DIM * PADD)         // 21504
#define OFF_VEC  (OFF_H + TS * PADH)             // 25728
#define OFF_W2   (OFF_VEC + TS * 12)             // 26496
#define OFF_MZT  (OFF_W2 + NQ * DIM)             // 26880
#define OFF_B1   (OFF_MZT + 5 * PADM + 3)        // 27208 (pad to mult of 4)
#define OFF_LNG  (OFF_B1 + DIM)
#define OFF_LNB  (OFF_LNG + DIM)
#define OFF_B2   (OFF_LNB + DIM)
#define OFF_BC   (OFF_B2 + 8)
#define SMEM_FLOATS (OFF_BC + 8)

__global__ __launch_bounds__(256, 2)
void qmaml_main_kernel(const float* __restrict__ x,
                       const float* __restrict__ W1,
                       const float* __restrict__ b1,
                       const float* __restrict__ lng,
                       const float* __restrict__ lnb,
                       const float* __restrict__ W2,
                       const float* __restrict__ b2,
                       const float* __restrict__ bc,
                       float* __restrict__ out,
                       int nTiles) {
    extern __shared__ float sm[];
    float* sW1T = sm + OFF_W1T;   // [j][i] pitch 68
    float* sCRT = sm + OFF_CRT;   // [j][i]
    float* sCIT = sm + OFF_CIT;   // [j][i]
    float* sAd  = sm + OFF_ADUP;  // [j][2s] duplicated a-operand, pitch 132
    float* sH   = sm + OFF_H;     // [s][i] pitch 66 (H, later probs)
    float* sVec = sm + OFF_VEC;   // [s][q][2]
    float* sW2  = sm + OFF_W2;    // [q][i]
    float* sMzT = sm + OFF_MZT;   // [o][i] pitch 65
    float* sB1  = sm + OFF_B1;
    float* sLnG = sm + OFF_LNG;
    float* sLnB = sm + OFF_LNB;
    float* sB2  = sm + OFF_B2;
    float* sBc  = sm + OFF_BC;

    const int tid = threadIdx.x;

    // ---- load weights once ----
    for (int idx = tid; idx < DIM * DIM; idx += 256) {
        int r = idx >> 6, c = idx & 63;
        sW1T[c * PADB + r] = W1[idx];
        sCRT[r * PADB + c] = g_CRT[idx];
        sCIT[r * PADB + c] = g_CIT[idx];
    }
    for (int idx = tid; idx < NQ * DIM; idx += 256) sW2[idx] = W2[idx];
    for (int idx = tid; idx < 5 * PADM; idx += 256) sMzT[idx] = g_MzT[idx];
    if (tid < DIM) { sB1[tid] = b1[tid]; sLnG[tid] = lng[tid]; sLnB[tid] = lnb[tid]; }
    if (tid < NQ) sB2[tid] = b2[tid];
    if (tid < 5) sBc[tid] = bc[tid];
    __syncthreads();

    const int tx = tid & 15, ty = tid >> 4;
    const int s0 = ty * 4, i0 = tx * 4;

    for (int tile = blockIdx.x; tile < nTiles; tile += gridDim.x) {
        const float4* xt4 = (const float4*)(x + (size_t)tile * TS * DIM);

        // ---- stage X duplicated: sAd[j][2s] = sAd[j][2s+1] = X[s][j] ----
        #pragma unroll
        for (int t = 0; t < 4; t++) {
            int idx = tid + t * 256;             // < 1024 float4
            float4 v = xt4[idx];
            int s = idx >> 4, j0 = (idx & 15) << 2;
            float2 d;
            d.x = v.x; d.y = v.x; *(float2*)(sAd + (j0 + 0) * PADD + 2 * s) = d;
            d.x = v.y; d.y = v.y; *(float2*)(sAd + (j0 + 1) * PADD + 2 * s) = d;
            d.x = v.z; d.y = v.z; *(float2*)(sAd + (j0 + 2) * PADD + 2 * s) = d;
            d.x = v.w; d.y = v.w; *(float2*)(sAd + (j0 + 3) * PADD + 2 * s) = d;
        }
        __syncthreads();

        // ---- GEMM1 (FFMA2) + fused LayerNorm epilogue ----
        {
            ull acc[4][2];
            #pragma unroll
            for (int k = 0; k < 4; k++) { acc[k][0] = 0ull; acc[k][1] = 0ull; }
            #pragma unroll 8
            for (int j = 0; j < DIM; j++) {
                ulonglong2 a01 = *(const ulonglong2*)(sAd + j * PADD + 2 * s0);
                ulonglong2 a23 = *(const ulonglong2*)(sAd + j * PADD + 2 * s0 + 4);
                ulonglong2 b   = *(const ulonglong2*)(sW1T + j * PADB + i0);
                ffma2(acc[0][0], a01.x, b.x); ffma2(acc[0][1], a01.x, b.y);
                ffma2(acc[1][0], a01.y, b.x); ffma2(acc[1][1], a01.y, b.y);
                ffma2(acc[2][0], a23.x, b.x); ffma2(acc[2][1], a23.x, b.y);
                ffma2(acc[3][0], a23.y, b.x); ffma2(acc[3][1], a23.y, b.y);
            }
            // unpack + bias + relu
            float h[4][4];
            float bb[4] = { sB1[i0], sB1[i0 + 1], sB1[i0 + 2], sB1[i0 + 3] };
            #pragma unroll
            for (int k = 0; k < 4; k++) {
                float2 f0 = *(float2*)&acc[k][0];
                float2 f1 = *(float2*)&acc[k][1];
                h[k][0] = fmaxf(f0.x + bb[0], 0.f);
                h[k][1] = fmaxf(f0.y + bb[1], 0.f);
                h[k][2] = fmaxf(f1.x + bb[2], 0.f);
                h[k][3] = fmaxf(f1.y + bb[3], 0.f);
            }
            // row reductions across the 16 tx-lanes (contiguous half-warp)
            float su[4], sq[4];
            #pragma unroll
            for (int k = 0; k < 4; k++) {
                su[k] = h[k][0] + h[k][1] + h[k][2] + h[k][3];
                sq[k] = h[k][0]*h[k][0] + h[k][1]*h[k][1]
                      + h[k][2]*h[k][2] + h[k][3]*h[k][3];
            }
            #pragma unroll
            for (int off = 1; off < 16; off <<= 1) {
                #pragma unroll
                for (int k = 0; k < 4; k++) {
                    su[k] += __shfl_xor_sync(0xffffffffu, su[k], off);
                    sq[k] += __shfl_xor_sync(0xffffffffu, sq[k], off);
                }
            }
            float gg[4] = { sLnG[i0], sLnG[i0+1], sLnG[i0+2], sLnG[i0+3] };
            float be[4] = { sLnB[i0], sLnB[i0+1], sLnB[i0+2], sLnB[i0+3] };
            #pragma unroll
            for (int k = 0; k < 4; k++) {
                float mu  = su[k] * (1.f / DIM);
                float var = sq[k] * (1.f / DIM) - mu * mu;
                float inv = rsqrtf(var + 1e-5f);
                float2 p0, p1;
                p0.x = (h[k][0] - mu) * inv * gg[0] + be[0];
                p0.y = (h[k][1] - mu) * inv * gg[1] + be[1];
                p1.x = (h[k][2] - mu) * inv * gg[2] + be[2];
                p1.y = (h[k][3] - mu) * inv * gg[3] + be[3];
                *(float2*)(sH + (s0 + k) * PADH + i0)     = p0;
                *(float2*)(sH + (s0 + k) * PADH + i0 + 2) = p1;
            }
        }
        __syncthreads();

        // ---- z = tanh(Hn @ W2^T + b2); vec = (cos,sin)(pi/2 z) ----
        for (int p = tid; p < TS * NQ; p += 256) {
            int s = p / NQ, q = p - s * NQ;
            const float* row = sH + s * PADH;
            const float* w2  = sW2 + q * DIM;
            float d = sB2[q];
            #pragma unroll 8
            for (int i = 0; i < DIM; i++) d += row[i] * w2[i];
            float z    = tanhf(d);
            float half = 1.5707963267948966f * z;
            float sn, cs;
            __sincosf(half, &sn, &cs);
            sVec[s * 12 + q * 2 + 0] = cs;
            sVec[s * 12 + q * 2 + 1] = sn;
        }
        __syncthreads();

        // ---- psi0 duplicated into sAd (overwrites X) ----
        {
            int s = tid >> 2, jb = (tid & 3) << 4;
            float v[NQ][2];
            #pragma unroll
            for (int q = 0; q < NQ; q++) {
                v[q][0] = sVec[s * 12 + q * 2 + 0];
                v[q][1] = sVec[s * 12 + q * 2 + 1];
            }
            #pragma unroll
            for (int j2 = 0; j2 < 16; j2++) {
                int jj = jb + j2;
                float p = v[0][(jj >> 5) & 1];
                p *= v[1][(jj >> 4) & 1];
                p *= v[2][(jj >> 3) & 1];
                p *= v[3][(jj >> 2) & 1];
                p *= v[4][(jj >> 1) & 1];
                p *= v[5][ jj       & 1];
                float2 d; d.x = p; d.y = p;
                *(float2*)(sAd + jj * PADD + 2 * s) = d;
            }
        }
        __syncthreads();

        // ---- GEMM2/3 (FFMA2): psiR/psiI = psi0 @ C^T ; probs -> sH ----
        {
            ull aR[4][2], aI[4][2];
            #pragma unroll
            for (int k = 0; k < 4; k++) {
                aR[k][0] = 0ull; aR[k][1] = 0ull;
                aI[k][0] = 0ull; aI[k][1] = 0ull;
            }
            #pragma unroll 8
            for (int j = 0; j < DIM; j++) {
                ulonglong2 a01 = *(const ulonglong2*)(sAd + j * PADD + 2 * s0);
                ulonglong2 a23 = *(const ulonglong2*)(sAd + j * PADD + 2 * s0 + 4);
                ulonglong2 br  = *(const ulonglong2*)(sCRT + j * PADB + i0);
                ulonglong2 bi  = *(const ulonglong2*)(sCIT + j * PADB + i0);
                ffma2(aR[0][0], a01.x, br.x); ffma2(aR[0][1], a01.x, br.y);
                ffma2(aR[1][0], a01.y, br.x); ffma2(aR[1][1], a01.y, br.y);
                ffma2(aR[2][0], a23.x, br.x); ffma2(aR[2][1], a23.x, br.y);
                ffma2(aR[3][0], a23.y, br.x); ffma2(aR[3][1], a23.y, br.y);
                ffma2(aI[0][0], a01.x, bi.x); ffma2(aI[0][1], a01.x, bi.y);
                ffma2(aI[1][0], a01.y, bi.x); ffma2(aI[1][1], a01.y, bi.y);
                ffma2(aI[2][0], a23.x, bi.x); ffma2(aI[2][1], a23.x, bi.y);
                ffma2(aI[3][0], a23.y, bi.x); ffma2(aI[3][1], a23.y, bi.y);
            }
            #pragma unroll
            for (int k = 0; k < 4; k++) {
                float2 r0 = *(float2*)&aR[k][0], r1 = *(float2*)&aR[k][1];
                float2 m0 = *(float2*)&aI[k][0], m1 = *(float2*)&aI[k][1];
                float2 p0, p1;
                p0.x = r0.x * r0.x + m0.x * m0.x;
                p0.y = r0.y * r0.y + m0.y * m0.y;
                p1.x = r1.x * r1.x + m1.x * m1.x;
                p1.y = r1.y * r1.y + m1.y * m1.y;
                *(float2*)(sH + (s0 + k) * PADH + i0)     = p0;
                *(float2*)(sH + (s0 + k) * PADH + i0 + 2) = p1;
            }
        }
        __syncthreads();

        // ---- out[s][o] = probs[s][:] . MzT[o][:] + bc[o] ----
        for (int p = tid; p < TS * 5; p += 256) {
            int s = p / 5, o = p - s * 5;
            const float* pr = sH + s * PADH;
            const float* mz = sMzT + o * PADM;
            float d = sBc[o];
            #pragma unroll 8
            for (int i = 0; i < DIM; i++) d += pr[i] * mz[i];
            out[((size_t)tile * TS + s) * 5 + o] = d;
        }
        __syncthreads();
    }
}

extern "C" void kernel_launch(void* const* d_in, const int* in_sizes, int n_in,
                              void* d_out, int out_size) {
    const float* x     = (const float*)d_in[0];
    const float* W1    = (const float*)d_in[1];
    const float* b1    = (const float*)d_in[2];
    const float* ln_g  = (const float*)d_in[3];
    const float* ln_b  = (const float*)d_in[4];
    const float* W2    = (const float*)d_in[5];
    const float* b2    = (const float*)d_in[6];
    const float* th_sh = (const float*)d_in[7];
    const float* th_tk = (const float*)d_in[8];
    const float* Wc    = (const float*)d_in[9];
    const float* bc    = (const float*)d_in[10];
    float* out = (float*)d_out;

    int B = in_sizes[0] / DIM;
    int nTiles = B / TS;

    setup_kernel<<<1, 64>>>(th_sh, th_tk, Wc);

    size_t smem = (size_t)SMEM_FLOATS * sizeof(float);
    cudaFuncSetAttribute(qmaml_main_kernel,
                         cudaFuncAttributeMaxDynamicSharedMemorySize, (int)smem);

    int grid = 296;
    if (grid > nTiles) grid = nTiles;
    qmaml_main_kernel<<<grid, 256, smem>>>(x, W1, b1, ln_g, ln_b, W2, b2, bc,
                                           out, nTiles);
}

// round 5
// speedup vs baseline: 1.5856x; 1.5856x over previous
#include <cuda_runtime.h>
#include <math.h>

#define NQ   6
#define DIM  64
#define SPT  256        // samples per iteration per block
#define PW   72         // weight pitch (words), with half-shift layout
#define PA   264        // aT pitch (words)

typedef unsigned long long ull;

__device__ float g_CRT[DIM * DIM];   // [j][i]
__device__ float g_CIT[DIM * DIM];   // [j][i]
__device__ float g_Mz[5 * DIM];      // [o][i]

__device__ __forceinline__ void ffma2(ull &d, ull a, ull b) {
    asm("fma.rn.f32x2 %0, %1, %2, %0;" : "+l"(d) : "l"(a), "l"(b));
}
__device__ __forceinline__ ull dup2(float v) {
    ull r; asm("mov.b64 %0, {%1, %1};" : "=l"(r) : "f"(v)); return r;
}
// half-shift: words i>=32 shifted +4 so 8 lanes at 32B stride hit distinct bank quads
__device__ __forceinline__ int ish(int i) { return i + ((i >> 5) << 2); }

__device__ __forceinline__ int ring_map(int r, int i) {
    int v = i;
    for (int w = NQ - 1; w >= 0; --w) {
        int t = (w + r) % NQ;
        v ^= ((v >> (NQ - 1 - w)) & 1) << (NQ - 1 - t);
    }
    return v;
}

// One block, 64 threads. Thread j owns column j of C.
__global__ void setup_kernel(const float* __restrict__ th_sh,
                             const float* __restrict__ th_tk,
                             const float* __restrict__ Wc) {
    __shared__ float2 C[DIM][DIM];
    int j = threadIdx.x;
    if (j >= DIM) return;
    for (int i = 0; i < DIM; i++) C[i][j] = make_float2(i == j ? 1.f : 0.f, 0.f);

    const float* TH[3] = { th_sh, th_sh + NQ * 3, th_tk };
    const int    RS[3] = { 1, 2, 1 };

    for (int l = 0; l < 3; l++) {
        const float* th = TH[l];
        for (int w = 0; w < NQ; w++) {
            float phi = th[w * 3 + 0], te = th[w * 3 + 1], om = th[w * 3 + 2];
            float sth, cth; sincosf(0.5f * te, &sth, &cth);
            float a = 0.5f * (phi + om), b = 0.5f * (phi - om);
            float sa, ca, sb, cb;
            sincosf(a, &sa, &ca);
            sincosf(b, &sb, &cb);
            float2 R00 = make_float2( ca * cth, -sa * cth);
            float2 R01 = make_float2(-cb * sth, -sb * sth);
            float2 R10 = make_float2( cb * sth, -sb * sth);
            float2 R11 = make_float2( ca * cth,  sa * cth);
            int bit = 1 << (NQ - 1 - w);
            for (int i0 = 0; i0 < DIM; i0++) {
                if (i0 & bit) continue;
                int i1 = i0 | bit;
                float2 v0 = C[i0][j], v1 = C[i1][j];
                C[i0][j] = make_float2(
                    R00.x * v0.x - R00.y * v0.y + R01.x * v1.x - R01.y * v1.y,
                    R00.x * v0.y + R00.y * v0.x + R01.x * v1.y + R01.y * v1.x);
                C[i1][j] = make_float2(
                    R10.x * v0.x - R10.y * v0.y + R11.x * v1.x - R11.y * v1.y,
                    R10.x * v0.y + R10.y * v0.x + R11.x * v1.y + R11.y * v1.x);
            }
        }
        float2 tmp[DIM];
        for (int i = 0; i < DIM; i++) tmp[i] = C[ring_map(RS[l], i)][j];
        for (int i = 0; i < DIM; i++) C[i][j] = tmp[i];
    }
    for (int i = 0; i < DIM; i++) {
        g_CRT[j * DIM + i] = C[i][j].x;
        g_CIT[j * DIM + i] = C[i][j].y;
    }
    for (int o = 0; o < 5; o++) {
        float s = 0.f;
        for (int q = 0; q < NQ; q++) {
            float zs = ((j >> (NQ - 1 - q)) & 1) ? -1.f : 1.f;
            s += zs * Wc[o * NQ + q];
        }
        g_Mz[o * DIM + j] = s;
    }
}

// smem layout (floats)
#define OFF_W1T  0
#define OFF_CRT  (OFF_W1T + DIM * PW)          // 4608
#define OFF_CIT  (OFF_CRT + DIM * PW)          // 9216
#define OFF_MZT  (OFF_CIT + DIM * PW)          // 13824
#define OFF_W2   (OFF_MZT + 5 * PW)            // 14184
#define OFF_B1   (OFF_W2 + NQ * DIM)           // 14568
#define OFF_LNG  (OFF_B1 + DIM)
#define OFF_LNB  (OFF_LNG + DIM)
#define OFF_B2   (OFF_LNB + DIM)
#define OFF_BC   (OFF_B2 + 8)
#define OFF_AT   (OFF_BC + 8)                  // 14776 (mult of 4 -> 16B aligned)
#define OFF_VEC  (OFF_AT + DIM * PA)           // 31672
#define SMEM_FLOATS (OFF_VEC + SPT * 13)       // 35000 -> 140 KB

// transpose-reduce: sum v[s] over 8 tx lanes; lane tx returns value for s == tx
__device__ __forceinline__ float txreduce8(float* v, int tx) {
    #pragma unroll
    for (int a = 0; a < 8; a++) v[a] += __shfl_xor_sync(0xffffffffu, v[a], 4);
    float v4[4];
    #pragma unroll
    for (int a = 0; a < 4; a++) v4[a] = (tx & 4) ? v[4 + a] : v[a];
    #pragma unroll
    for (int a = 0; a < 4; a++) v4[a] += __shfl_xor_sync(0xffffffffu, v4[a], 2);
    float v2[2];
    #pragma unroll
    for (int a = 0; a < 2; a++) v2[a] = (tx & 2) ? v4[2 + a] : v4[a];
    #pragma unroll
    for (int a = 0; a < 2; a++) v2[a] += __shfl_xor_sync(0xffffffffu, v2[a], 1);
    return (tx & 1) ? v2[1] : v2[0];
}

__global__ __launch_bounds__(256, 1)
void qmaml_main_kernel(const float* __restrict__ x,
                       const float* __restrict__ W1,
                       const float* __restrict__ b1,
                       const float* __restrict__ lng,
                       const float* __restrict__ lnb,
                       const float* __restrict__ W2,
                       const float* __restrict__ b2,
                       const float* __restrict__ bc,
                       float* __restrict__ out,
                       int nIter) {
    extern __shared__ float sm[];
    float* sW1T = sm + OFF_W1T;   // [j][ish(i)]
    float* sCRT = sm + OFF_CRT;
    float* sCIT = sm + OFF_CIT;
    float* sMzT = sm + OFF_MZT;   // [o][ish(i)]
    float* sW2  = sm + OFF_W2;    // [q][i] linear
    float* sB1  = sm + OFF_B1;
    float* sLnG = sm + OFF_LNG;
    float* sLnB = sm + OFF_LNB;
    float* sB2  = sm + OFF_B2;
    float* sBc  = sm + OFF_BC;
    float* sAT  = sm + OFF_AT;    // [j][rot(s)] pitch 264
    float* sVec = sm + OFF_VEC;   // [s][13]

    const int tid = threadIdx.x;

    // ---- load weights once ----
    for (int idx = tid; idx < DIM * DIM; idx += 256) {
        int j = idx >> 6, i = idx & 63;
        int d = j * PW + ish(i);
        sW1T[d] = W1[i * DIM + j];    // W1 [i][j] row-major -> [j][i]
        sCRT[d] = g_CRT[idx];         // already [j][i]
        sCIT[d] = g_CIT[idx];
    }
    for (int idx = tid; idx < 5 * DIM; idx += 256) {
        int o = idx >> 6, i = idx & 63;
        sMzT[o * PW + ish(i)] = g_Mz[idx];
    }
    for (int idx = tid; idx < NQ * DIM; idx += 256) sW2[idx] = W2[idx];
    if (tid < DIM) { sB1[tid] = b1[tid]; sLnG[tid] = lng[tid]; sLnB[tid] = lnb[tid]; }
    if (tid < NQ) sB2[tid] = b2[tid];
    if (tid < 5) sBc[tid] = bc[tid];
    __syncthreads();

    const int tx = tid & 7, ty = tid >> 3;
    const int i0 = tx * 8, s0 = ty * 8;
    const int ish0 = ish(i0);

    for (int iter = blockIdx.x; iter < nIter; iter += gridDim.x) {
        const float4* xg = (const float4*)(x + (size_t)iter * SPT * DIM);

        // ---- stage X^T into sAT[j][rot_j(s)] ----
        #pragma unroll
        for (int t = 0; t < 16; t++) {
            int idx = tid + t * 256;             // 4096 float4
            float4 v = xg[idx];
            int s = idx >> 4, j0 = (idx & 15) << 2;
            int rs = (s + ((idx & 3) << 3)) & 255;   // rot = 8*((j>>2)&3), j>>2 == idx&15
            sAT[(j0 + 0) * PA + rs] = v.x;
            sAT[(j0 + 1) * PA + rs] = v.y;
            sAT[(j0 + 2) * PA + rs] = v.z;
            sAT[(j0 + 3) * PA + rs] = v.w;
        }
        __syncthreads();

        // ---- GEMM1: acc[s][ipair] over j ----
        ull acc[8][4];
        #pragma unroll
        for (int s = 0; s < 8; s++)
            #pragma unroll
            for (int q = 0; q < 4; q++) acc[s][q] = 0ull;

        #pragma unroll 4
        for (int j = 0; j < DIM; j++) {
            const float* ap = sAT + j * PA + ((s0 + (((j >> 2) & 3) << 3)) & 255);
            float4 al = *(const float4*)ap;
            float4 ah = *(const float4*)(ap + 4);
            const float* bp = sW1T + j * PW + ish0;
            ulonglong2 b01 = *(const ulonglong2*)bp;
            ulonglong2 b23 = *(const ulonglong2*)(bp + 4);
            ull ad[8];
            ad[0] = dup2(al.x); ad[1] = dup2(al.y); ad[2] = dup2(al.z); ad[3] = dup2(al.w);
            ad[4] = dup2(ah.x); ad[5] = dup2(ah.y); ad[6] = dup2(ah.z); ad[7] = dup2(ah.w);
            #pragma unroll
            for (int s = 0; s < 8; s++) {
                ffma2(acc[s][0], ad[s], b01.x);
                ffma2(acc[s][1], ad[s], b01.y);
                ffma2(acc[s][2], ad[s], b23.x);
                ffma2(acc[s][3], ad[s], b23.y);
            }
        }

        // ---- bias + relu + LayerNorm (registers + shfl) ----
        float h[8][8];
        {
            float bb[8], gg[8], be[8];
            #pragma unroll
            for (int c = 0; c < 8; c++) {
                bb[c] = sB1[i0 + c]; gg[c] = sLnG[i0 + c]; be[c] = sLnB[i0 + c];
            }
            #pragma unroll
            for (int s = 0; s < 8; s++)
                #pragma unroll
                for (int q = 0; q < 4; q++) {
                    float2 f = *(float2*)&acc[s][q];
                    h[s][2 * q]     = fmaxf(f.x + bb[2 * q], 0.f);
                    h[s][2 * q + 1] = fmaxf(f.y + bb[2 * q + 1], 0.f);
                }
            float su[8], sq[8];
            #pragma unroll
            for (int s = 0; s < 8; s++) {
                float a = 0.f, b = 0.f;
                #pragma unroll
                for (int c = 0; c < 8; c++) { a += h[s][c]; b += h[s][c] * h[s][c]; }
                su[s] = a; sq[s] = b;
            }
            #pragma unroll
            for (int off = 1; off < 8; off <<= 1)
                #pragma unroll
                for (int s = 0; s < 8; s++) {
                    su[s] += __shfl_xor_sync(0xffffffffu, su[s], off);
                    sq[s] += __shfl_xor_sync(0xffffffffu, sq[s], off);
                }
            #pragma unroll
            for (int s = 0; s < 8; s++) {
                float mu  = su[s] * (1.f / DIM);
                float var = sq[s] * (1.f / DIM) - mu * mu;
                float inv = rsqrtf(var + 1e-5f);
                #pragma unroll
                for (int c = 0; c < 8; c++)
                    h[s][c] = (h[s][c] - mu) * inv * gg[c] + be[c];
            }
        }

        // ---- z = tanh(Hn @ W2^T + b2): partials + transpose-reduce ----
        {
            float zp[8][NQ];
            #pragma unroll
            for (int q = 0; q < NQ; q++) {
                float4 wa = *(const float4*)(sW2 + q * DIM + i0);
                float4 wb = *(const float4*)(sW2 + q * DIM + i0 + 4);
                float w[8] = { wa.x, wa.y, wa.z, wa.w, wb.x, wb.y, wb.z, wb.w };
                #pragma unroll
                for (int s = 0; s < 8; s++) {
                    float d = 0.f;
                    #pragma unroll
                    for (int c = 0; c < 8; c++) d += h[s][c] * w[c];
                    zp[s][q] = d;
                }
            }
            int sg = s0 + tx;   // lane tx owns sample s0+tx after reduce
            #pragma unroll
            for (int q = 0; q < NQ; q++) {
                float v[8];
                #pragma unroll
                for (int s = 0; s < 8; s++) v[s] = zp[s][q];
                float zs = txreduce8(v, tx);
                float z    = tanhf(zs + sB2[q]);
                float half = 1.5707963267948966f * z;
                float sn, cs;
                __sincosf(half, &sn, &cs);
                sVec[sg * 13 + 2 * q]     = cs;
                sVec[sg * 13 + 2 * q + 1] = sn;
            }
        }
        __syncthreads();

        // ---- psi0: thread = sample, build 64 amplitudes, store transposed ----
        {
            int s = tid;
            const float* vv = sVec + s * 13;
            float p1[2], p2[4], p3[8], p4[16], p5[32], p6[64];
            p1[0] = vv[0]; p1[1] = vv[1];
            #pragma unroll
            for (int k = 0; k < 2; k++) { p2[2*k] = p1[k]*vv[2]; p2[2*k+1] = p1[k]*vv[3]; }
            #pragma unroll
            for (int k = 0; k < 4; k++) { p3[2*k] = p2[k]*vv[4]; p3[2*k+1] = p2[k]*vv[5]; }
            #pragma unroll
            for (int k = 0; k < 8; k++) { p4[2*k] = p3[k]*vv[6]; p4[2*k+1] = p3[k]*vv[7]; }
            #pragma unroll
            for (int k = 0; k < 16; k++) { p5[2*k] = p4[k]*vv[8]; p5[2*k+1] = p4[k]*vv[9]; }
            #pragma unroll
            for (int k = 0; k < 32; k++) { p6[2*k] = p5[k]*vv[10]; p6[2*k+1] = p5[k]*vv[11]; }
            #pragma unroll
            for (int j = 0; j < DIM; j++)
                sAT[j * PA + ((s + (((j >> 2) & 3) << 3)) & 255)] = p6[j];
        }
        __syncthreads();

        // ---- GEMM2/3: psiR/psiI = psi0 @ C^T ----
        ull aR[8][4], aI[8][4];
        #pragma unroll
        for (int s = 0; s < 8; s++)
            #pragma unroll
            for (int q = 0; q < 4; q++) { aR[s][q] = 0ull; aI[s][q] = 0ull; }

        #pragma unroll 4
        for (int j = 0; j < DIM; j++) {
            const float* ap = sAT + j * PA + ((s0 + (((j >> 2) & 3) << 3)) & 255);
            float4 al = *(const float4*)ap;
            float4 ah = *(const float4*)(ap + 4);
            const float* rp = sCRT + j * PW + ish0;
            const float* ip = sCIT + j * PW + ish0;
            ulonglong2 r01 = *(const ulonglong2*)rp;
            ulonglong2 r23 = *(const ulonglong2*)(rp + 4);
            ulonglong2 i01 = *(const ulonglong2*)ip;
            ulonglong2 i23 = *(const ulonglong2*)(ip + 4);
            ull ad[8];
            ad[0] = dup2(al.x); ad[1] = dup2(al.y); ad[2] = dup2(al.z); ad[3] = dup2(al.w);
            ad[4] = dup2(ah.x); ad[5] = dup2(ah.y); ad[6] = dup2(ah.z); ad[7] = dup2(ah.w);
            #pragma unroll
            for (int s = 0; s < 8; s++) {
                ffma2(aR[s][0], ad[s], r01.x);
                ffma2(aR[s][1], ad[s], r01.y);
                ffma2(aR[s][2], ad[s], r23.x);
                ffma2(aR[s][3], ad[s], r23.y);
                ffma2(aI[s][0], ad[s], i01.x);
                ffma2(aI[s][1], ad[s], i01.y);
                ffma2(aI[s][2], ad[s], i23.x);
                ffma2(aI[s][3], ad[s], i23.y);
            }
        }

        // ---- probs (packed) -> Mz partials -> transpose-reduce -> gmem ----
        {
            ulonglong2 mza[5], mzb[5];
            #pragma unroll
            for (int o = 0; o < 5; o++) {
                const float* mp = sMzT + o * PW + ish0;
                mza[o] = *(const ulonglong2*)mp;
                mzb[o] = *(const ulonglong2*)(mp + 4);
            }
            float vals[8][5];
            #pragma unroll
            for (int s = 0; s < 8; s++) {
                ull pp[4];
                #pragma unroll
                for (int q = 0; q < 4; q++) {
                    pp[q] = 0ull;
                    ffma2(pp[q], aR[s][q], aR[s][q]);
                    ffma2(pp[q], aI[s][q], aI[s][q]);
                }
                #pragma unroll
                for (int o = 0; o < 5; o++) {
                    ull a5 = 0ull;
                    ffma2(a5, pp[0], mza[o].x);
                    ffma2(a5, pp[1], mza[o].y);
                    ffma2(a5, pp[2], mzb[o].x);
                    ffma2(a5, pp[3], mzb[o].y);
                    float2 f = *(float2*)&a5;
                    vals[s][o] = f.x + f.y;
                }
            }
            int sg = iter * SPT + s0 + tx;
            #pragma unroll
            for (int o = 0; o < 5; o++) {
                float v[8];
                #pragma unroll
                for (int s = 0; s < 8; s++) v[s] = vals[s][o];
                float r = txreduce8(v, tx);
                out[(size_t)sg * 5 + o] = r + sBc[o];
            }
        }
        __syncthreads();   // protect sAT before next iteration
    }
}

extern "C" void kernel_launch(void* const* d_in, const int* in_sizes, int n_in,
                              void* d_out, int out_size) {
    const float* x     = (const float*)d_in[0];
    const float* W1    = (const float*)d_in[1];
    const float* b1    = (const float*)d_in[2];
    const float* ln_g  = (const float*)d_in[3];
    const float* ln_b  = (const float*)d_in[4];
    const float* W2    = (const float*)d_in[5];
    const float* b2    = (const float*)d_in[6];
    const float* th_sh = (const float*)d_in[7];
    const float* th_tk = (const float*)d_in[8];
    const float* Wc    = (const float*)d_in[9];
    const float* bc    = (const float*)d_in[10];
    float* out = (float*)d_out;

    int B = in_sizes[0] / DIM;
    int nIter = B / SPT;

    setup_kernel<<<1, 64>>>(th_sh, th_tk, Wc);

    size_t smem = (size_t)SMEM_FLOATS * sizeof(float);
    cudaFuncSetAttribute(qmaml_main_kernel,
                         cudaFuncAttributeMaxDynamicSharedMemorySize, (int)smem);

    int grid = 148;
    if (grid > nIter) grid = nIter;
    qmaml_main_kernel<<<grid, 256, smem>>>(x, W1, b1, ln_g, ln_b, W2, b2, bc,
                                           out, nIter);
}